// round 15
// baseline (speedup 1.0000x reference)
#include <cuda_runtime.h>
#include <cuda_fp16.h>
#include <cstdint>
#include <cfloat>

// Fused conv2d 3x3 SAME -> min over C_out -> *2 via pipelined mma.sync FP16
// (m16n8k16, f32 accumulate). x:(32,64,128,128) f32, W:(128,64,3,3) f32.
//
// Round 15 = R14 with CTA M doubled to 256 (two output rows, 512 threads,
// 16 warps 4m x 4n, warp tile still 64x32 -> acc stays 64 regs/thread):
//  - A slab: 32 slots (4 gy-rows x 8 ic-planes), rows y0-1..y0+2 serve both
//    output rows and all ky -> A fill per output x2/3, B fill per output x1/2
//  - chunk = ic-group (16 ic, 9 k16-steps); 4 chunks; boundary costs amortize 2x
//  - 1 CTA/SM (112.6KB smem), same 16 warps/SM as R14

#define TPB 512

static constexpr int SLOT_B = 544;                   // 136 half2 words
static constexpr int A_BUF  = 32 * SLOT_B;           // 17408 (4 rows x 8 planes)
static constexpr int B_OFF  = 2 * A_BUF;             // 34816
static constexpr int B_SLAB = 9 * 4096;              // 36864
static constexpr int RED_OFF = B_OFF + 2 * B_SLAB;   // 108544
static constexpr int SMEM_TOTAL = RED_OFF + 4096;    // 112640

static constexpr int IMG_ROW  = 272;                 // halves per padded row
static constexpr int ICG_STRH = 8 * 128 * IMG_ROW;   // halves per 8-plane group

__device__ __half x16i[35651584];   // 32 b x 32 planes x 128 rows x 272 halves
__device__ __half W2h[4 * 18432];

__device__ __forceinline__ uint32_t smem_u32(const void* p) {
    uint32_t a;
    asm("{ .reg .u64 t; cvta.to.shared.u64 t, %1; cvt.u32.u64 %0, t; }" : "=r"(a) : "l"(p));
    return a;
}
__device__ __forceinline__ uint32_t lds32(uint32_t a) {
    uint32_t v;
    asm volatile("ld.shared.b32 %0, [%1];" : "=r"(v) : "r"(a));
    return v;
}
__device__ __forceinline__ void mma_f16(float& d0, float& d1, float& d2, float& d3,
                                        uint32_t a0, uint32_t a1, uint32_t a2, uint32_t a3,
                                        uint32_t b0, uint32_t b1) {
    asm volatile(
        "mma.sync.aligned.m16n8k16.row.col.f32.f16.f16.f32 "
        "{%0,%1,%2,%3}, {%4,%5,%6,%7}, {%8,%9}, {%0,%1,%2,%3};"
        : "+f"(d0), "+f"(d1), "+f"(d2), "+f"(d3)
        : "r"(a0), "r"(a1), "r"(a2), "r"(a3), "r"(b0), "r"(b1));
}

// ---- pre-kernel 1: x -> ic-interleaved padded fp16 image (as R13/R14) ----
__global__ void xi_kernel(const float* __restrict__ x) {
    int idx = blockIdx.x * 256 + threadIdx.x;       // 16B chunk = 4 words
    int w4 = idx % 34;
    int rr = idx / 34;
    int gy = rr & 127;
    int rr2 = rr >> 7;
    int p = rr2 & 31;
    int b = rr2 >> 5;
    const float* s0 = x + ((size_t)(b * 64 + 2 * p) * 128 + gy) * 128;
    const float* s1 = s0 + 16384;
    uint32_t w[4];
#pragma unroll
    for (int j = 0; j < 4; ++j) {
        int c = w4 * 4 + j - 1;
        float lo = 0.f, hi = 0.f;
        if ((unsigned)c < 128u) { lo = s0[c]; hi = s1[c]; }
        __half2 h = __floats2half2_rn(lo, hi);
        w[j] = *reinterpret_cast<uint32_t*>(&h);
    }
    uint4 u = make_uint4(w[0], w[1], w[2], w[3]);
    size_t off = ((size_t)(b * 32 + p) * 128 + gy) * IMG_ROW + (size_t)w4 * 8;
    *reinterpret_cast<uint4*>(x16i + off) = u;
}

// ---- pre-kernel 2: W -> fragment-ordered fp16 W2h (identical to R14) ----
__global__ void wxform_kernel(const float* __restrict__ Wt) {
    int f = blockIdx.x * 256 + threadIdx.x;
    if (f >= 4 * 18432) return;
    int c = f / 18432;
    int r = f - c * 18432;
    int st = r >> 11;
    int u  = r & 2047;
    int ky = st / 3, kx = st - 3 * ky;
    int unit = u >> 3, h = u & 7;
    int lane = unit & 31, rest = unit >> 5;
    int wn = rest >> 1, j = rest & 1;
    int word = h >> 1, hw = h & 1;
    int nt = wn * 4 + j * 2 + (word >> 1);
    int breg = word & 1;
    int t = lane & 3, q = lane >> 2;
    int oc  = nt * 8 + q;
    int ipl = t + 4 * breg;
    int ic  = c * 16 + ipl * 2 + hw;
    W2h[f] = __float2half_rn(Wt[oc * 576 + ic * 9 + ky * 3 + kx]);
}

__global__ void __launch_bounds__(TPB, 1)
conv_min_mma12_kernel(float* __restrict__ out)
{
    extern __shared__ char smem[];
    const uint32_t sb = smem_u32(smem);
    const int tid    = threadIdx.x;
    const int lane   = tid & 31;
    const int wid    = tid >> 5;
    const int warp_m = wid >> 2;   // 0..3: ri = warp_m>>1, px half = warp_m&1
    const int warp_n = wid & 3;    // 0..3
    const int q = lane >> 2;
    const int t = lane & 3;
    const int ri  = warp_m >> 1;
    const int y0  = blockIdx.x * 2;
    const int b   = blockIdx.y;

    // per-lane A gather base: plane slot t, word ((warp_m&1)*64 + q)
    const uint32_t laneA = (uint32_t)(t * SLOT_B + ((warp_m & 1) * 64 + q) * 4);

    // ---- per-thread A-fill descriptors: 1088 16B-chunks per ic-group ----
    const __half* f_src[3];
    uint32_t f_dst[3];
    bool f_ok[3], f_val[3];
#pragma unroll
    for (int i = 0; i < 3; ++i) {
        int ch = tid + TPB * i;
        f_val[i] = (ch < 1088);
        int chc  = f_val[i] ? ch : 0;
        int slot = chc / 34, w4 = chc - slot * 34;
        int r4 = slot >> 3, ipl = slot & 7;
        int gy = y0 + r4 - 1;
        f_ok[i]  = f_val[i] && ((unsigned)gy < 128u);
        f_dst[i] = (uint32_t)(slot * SLOT_B + w4 * 16);
        f_src[i] = f_ok[i]
            ? x16i + (((size_t)(b * 32 + ipl) * 128 + gy) * IMG_ROW + (size_t)w4 * 8)
            : x16i;
    }

    float acc[4][4][4];
#pragma unroll
    for (int mt = 0; mt < 4; ++mt)
#pragma unroll
        for (int nt = 0; nt < 4; ++nt)
#pragma unroll
            for (int r = 0; r < 4; ++r) acc[mt][nt][r] = 0.0f;

    // ---- prologue: group0 = A(0)+B(0); group1 = A(1)+B(1) ----
#pragma unroll
    for (int cc = 0; cc < 2; ++cc) {
        size_t adv = (size_t)cc * ICG_STRH;
        uint32_t ab = sb + (uint32_t)(cc * A_BUF);
#pragma unroll
        for (int i = 0; i < 3; ++i) {
            if (f_val[i]) {
                const __half* sp = f_ok[i] ? (f_src[i] + adv) : x16i;
                uint32_t sz = f_ok[i] ? 16u : 0u;
                uint64_t g64 = __cvta_generic_to_global((const void*)sp);
                asm volatile("cp.async.cg.shared.global [%0], [%1], 16, %2;"
                             :: "r"(ab + f_dst[i]), "l"(g64), "r"(sz) : "memory");
            }
        }
        uint32_t bdst = sb + B_OFF + (uint32_t)(cc * B_SLAB);
        const __half* bsrc = W2h + cc * 18432;
#pragma unroll
        for (int i = 0; i < 5; ++i) {
            int j = tid + TPB * i;
            if (j < 2304) {
                uint64_t g64 = __cvta_generic_to_global((const void*)(bsrc + j * 8));
                asm volatile("cp.async.cg.shared.global [%0], [%1], 16;"
                             :: "r"(bdst + (uint32_t)(j * 16)), "l"(g64) : "memory");
            }
        }
        asm volatile("cp.async.commit_group;" ::: "memory");
    }

#pragma unroll 1
    for (int c = 0; c < 4; ++c) {
        asm volatile("cp.async.wait_group 1;" ::: "memory");
        __syncthreads();

        // ---- compute chunk c: 9 k16-steps (ky, kx) ----
        const uint32_t aC = sb + (uint32_t)((c & 1) * A_BUF) + laneA;
        const uint32_t bC = sb + B_OFF + (uint32_t)((c & 1) * B_SLAB) +
                            (uint32_t)(warp_n * 1024 + lane * 16);
#pragma unroll
        for (int ky = 0; ky < 3; ++ky) {
            const uint32_t aKy = aC + (uint32_t)((ri + ky) * (8 * SLOT_B));
#pragma unroll
            for (int kx = 0; kx < 3; ++kx) {
                const uint32_t aS = aKy + (uint32_t)(kx * 4);
                const uint32_t bS = bC + (uint32_t)((ky * 3 + kx) * 4096);
                uint32_t a0[4], a1[4], a2[4], a3[4];
#pragma unroll
                for (int mt = 0; mt < 4; ++mt) {
                    uint32_t base = aS + (uint32_t)(mt * 64);
                    a0[mt] = lds32(base);
                    a1[mt] = lds32(base + 32);
                    a2[mt] = lds32(base + 4 * SLOT_B);
                    a3[mt] = lds32(base + 4 * SLOT_B + 32);
                }
                uint32_t b0[4], b1[4];
#pragma unroll
                for (int j = 0; j < 2; ++j) {
                    uint32_t addr = bS + (uint32_t)(j * 512);
                    asm volatile("ld.shared.v4.b32 {%0,%1,%2,%3}, [%4];"
                                 : "=r"(b0[2 * j]), "=r"(b1[2 * j]),
                                   "=r"(b0[2 * j + 1]), "=r"(b1[2 * j + 1])
                                 : "r"(addr));
                }
#pragma unroll
                for (int mt = 0; mt < 4; ++mt)
#pragma unroll
                    for (int nt = 0; nt < 4; ++nt)
                        mma_f16(acc[mt][nt][0], acc[mt][nt][1],
                                acc[mt][nt][2], acc[mt][nt][3],
                                a0[mt], a1[mt], a2[mt], a3[mt], b0[nt], b1[nt]);
            }
        }

        // all warps done reading parity-c buffers -> safe to refill
        __syncthreads();
        if (c + 2 < 4) {
            size_t adv = (size_t)(c + 2) * ICG_STRH;
            uint32_t ab = sb + (uint32_t)((c & 1) * A_BUF);
#pragma unroll
            for (int i = 0; i < 3; ++i) {
                if (f_val[i]) {
                    const __half* sp = f_ok[i] ? (f_src[i] + adv) : x16i;
                    uint32_t sz = f_ok[i] ? 16u : 0u;
                    uint64_t g64 = __cvta_generic_to_global((const void*)sp);
                    asm volatile("cp.async.cg.shared.global [%0], [%1], 16, %2;"
                                 :: "r"(ab + f_dst[i]), "l"(g64), "r"(sz) : "memory");
                }
            }
            uint32_t bdst = sb + B_OFF + (uint32_t)((c & 1) * B_SLAB);
            const __half* bsrc = W2h + (c + 2) * 18432;
#pragma unroll
            for (int i = 0; i < 5; ++i) {
                int j = tid + TPB * i;
                if (j < 2304) {
                    uint64_t g64 = __cvta_generic_to_global((const void*)(bsrc + j * 8));
                    asm volatile("cp.async.cg.shared.global [%0], [%1], 16;"
                                 :: "r"(bdst + (uint32_t)(j * 16)), "l"(g64) : "memory");
                }
            }
        }
        asm volatile("cp.async.commit_group;" ::: "memory");
    }

    // ---- epilogue: min over oc, *2, write 2 rows ----
    float rmin[4][2];
#pragma unroll
    for (int mt = 0; mt < 4; ++mt) {
        float lo = fminf(acc[mt][0][0], acc[mt][0][1]);
        float hi = fminf(acc[mt][0][2], acc[mt][0][3]);
#pragma unroll
        for (int nt = 1; nt < 4; ++nt) {
            lo = fminf(lo, fminf(acc[mt][nt][0], acc[mt][nt][1]));
            hi = fminf(hi, fminf(acc[mt][nt][2], acc[mt][nt][3]));
        }
        rmin[mt][0] = lo;
        rmin[mt][1] = hi;
    }
#pragma unroll
    for (int d = 1; d <= 2; d <<= 1)
#pragma unroll
        for (int mt = 0; mt < 4; ++mt)
#pragma unroll
            for (int h = 0; h < 2; ++h)
                rmin[mt][h] = fminf(rmin[mt][h],
                                    __shfl_xor_sync(0xffffffffu, rmin[mt][h], d));

    float* red = reinterpret_cast<float*>(smem + RED_OFF);
    __syncthreads();
    if ((lane & 3) == 0) {
        int gq = lane >> 2;
#pragma unroll
        for (int mt = 0; mt < 4; ++mt)
#pragma unroll
            for (int h = 0; h < 2; ++h) {
                int row = warp_m * 64 + mt * 16 + h * 8 + gq;   // 0..255
                red[row * 4 + warp_n] = rmin[mt][h];
            }
    }
    __syncthreads();
    if (tid < 256) {
        float m = fminf(fminf(red[tid * 4 + 0], red[tid * 4 + 1]),
                        fminf(red[tid * 4 + 2], red[tid * 4 + 3]));
        int rr = tid >> 7, px = tid & 127;
        out[(size_t)b * 16384 + (y0 + rr) * 128 + px] = m * 2.0f;
    }
}

extern "C" void kernel_launch(void* const* d_in, const int* in_sizes, int n_in,
                              void* d_out, int out_size)
{
    const float* x  = (const float*)d_in[0];
    const float* Wt = (const float*)d_in[1];
    float* out = (float*)d_out;

    cudaFuncSetAttribute(conv_min_mma12_kernel,
                         cudaFuncAttributeMaxDynamicSharedMemorySize, SMEM_TOTAL);

    xi_kernel<<<17408, 256>>>(x);                            // 32*32*128*34 / 256
    wxform_kernel<<<(4 * 18432 + 255) / 256, 256>>>(Wt);

    dim3 grid(64, 32);   // row-pairs x batch
    conv_min_mma12_kernel<<<grid, TPB, SMEM_TOTAL>>>(out);
}